// round 14
// baseline (speedup 1.0000x reference)
#include <cuda_runtime.h>
#include <math.h>

#define NS 1024
#define NR 4096
#define NSM 148
#define GRIDP (2 * NSM)    // 296 blocks, exactly 2 per SM (co-residency guaranteed)
#define TPB 256
#define NITEMS (NS * 4)    // work item = quarter sample (1024 residues)

// ---------------- scratch (static device globals; no allocation) ----------------
__device__ __align__(16) float4 g_wt4[NR];  // (w*t_c0, w*t_c1, w*t_c2, w)
__device__ float g_stats[8];                // [4]=1/Lt, [5]=1/d0^2
__device__ float g_Spart[NITEMS * 12];      // per item: S(9), P(3)
__device__ float g_RT[NS * 12];             // per sample: R(9), c(3)
__device__ float g_tmpart[NITEMS];          // per item TM partial
__device__ unsigned g_ctrA, g_ctrB;         // work queues (reset by k_pre)
__device__ unsigned g_barA = 0, g_barG = 0;

__device__ __forceinline__ float warpsum(float v) {
#pragma unroll
    for (int o = 16; o; o >>= 1) v += __shfl_down_sync(0xffffffffu, v, o);
    return v;
}

__device__ __forceinline__ float rcp_fast(float x) {
    float r;
    asm("rcp.approx.f32 %0, %1;" : "=f"(r) : "f"(x));
    return r;
}

// sense-reversing grid barrier; safe: all GRIDP blocks co-resident
__device__ __forceinline__ void grid_barrier() {
    __threadfence();
    __syncthreads();
    if (threadIdx.x == 0) {
        unsigned gen = atomicAdd(&g_barG, 0u);
        unsigned t = atomicAdd(&g_barA, 1u);
        if (t == GRIDP - 1) {
            atomicExch(&g_barA, 0u);
            __threadfence();
            atomicAdd(&g_barG, 1u);
        } else {
            while (atomicAdd(&g_barG, 0u) == gen) __nanosleep(64);
        }
    }
    __syncthreads();
}

// ---------------- kernel A: true stats + wt4 companion + counter reset ----------
#define PRE_T 1024
__global__ void k_pre(const float* __restrict__ truec, const int* __restrict__ mask) {
    int tid = threadIdx.x;
    if (tid == 0) { g_ctrA = 0u; g_ctrB = 0u; }
    float ws = 0.f, wt0 = 0.f, wt1 = 0.f, wt2 = 0.f;
    for (int l = tid; l < NR; l += PRE_T) {
        float w = (mask[l] != 0) ? 1.0f : 0.0f;
        ws += w;
        wt0 += w * truec[l * 3 + 0];
        wt1 += w * truec[l * 3 + 1];
        wt2 += w * truec[l * 3 + 2];
    }
    __shared__ float sm[4][32];
    __shared__ float s_tm[3];
    int lane = tid & 31, wid = tid >> 5;
    ws = warpsum(ws); wt0 = warpsum(wt0); wt1 = warpsum(wt1); wt2 = warpsum(wt2);
    if (lane == 0) { sm[0][wid] = ws; sm[1][wid] = wt0; sm[2][wid] = wt1; sm[3][wid] = wt2; }
    __syncthreads();
    if (tid == 0) {
        float Lt = 0.f, a = 0.f, b = 0.f, c = 0.f;
        for (int i = 0; i < 32; i++) { Lt += sm[0][i]; a += sm[1][i]; b += sm[2][i]; c += sm[3][i]; }
        float inv = 1.0f / Lt;
        float d0 = (Lt <= 15.0f) ? 0.5f : (1.24f * cbrtf(Lt - 15.0f) - 1.8f);
        d0 = fmaxf(d0, 0.5f);
        g_stats[0] = a * inv; g_stats[1] = b * inv; g_stats[2] = c * inv;
        g_stats[3] = Lt; g_stats[4] = inv; g_stats[5] = 1.0f / (d0 * d0);
        s_tm[0] = a * inv; s_tm[1] = b * inv; s_tm[2] = c * inv;
    }
    __syncthreads();
    float m0 = s_tm[0], m1 = s_tm[1], m2 = s_tm[2];
    for (int l = tid; l < NR; l += PRE_T) {
        float w = (mask[l] != 0) ? 1.0f : 0.0f;
        float4 v;
        v.x = w * (truec[l * 3 + 0] - m0);
        v.y = w * (truec[l * 3 + 1] - m1);
        v.z = w * (truec[l * 3 + 2] - m2);
        v.w = w;
        g_wt4[l] = v;
    }
}

// ---------------- main persistent kernel ----------------------------------------
// chunk: 96 pred float4 (128 residues); lane handles 4 residues = 3 pred f4 + 4 comp f4
struct Ck { float4 p0, p1, p2, q0, q1, q2, q3; };

#define LOADC(C_, pp_, rb_, c_) do { \
    int o_ = (c_) * 96 + 3 * lane; \
    (C_).p0 = (pp_)[o_]; (C_).p1 = (pp_)[o_ + 1]; (C_).p2 = (pp_)[o_ + 2]; \
    int r_ = (rb_) + (c_) * 128 + 4 * lane; \
    (C_).q0 = g_wt4[r_]; (C_).q1 = g_wt4[r_ + 1]; \
    (C_).q2 = g_wt4[r_ + 2]; (C_).q3 = g_wt4[r_ + 3]; } while (0)

#define CRES(qq, px, py, pz) do { \
    S00 = fmaf((px), (qq).x, S00); S01 = fmaf((px), (qq).y, S01); S02 = fmaf((px), (qq).z, S02); \
    S10 = fmaf((py), (qq).x, S10); S11 = fmaf((py), (qq).y, S11); S12 = fmaf((py), (qq).z, S12); \
    S20 = fmaf((pz), (qq).x, S20); S21 = fmaf((pz), (qq).y, S21); S22 = fmaf((pz), (qq).z, S22); \
    P0 = fmaf((qq).w, (px), P0); P1 = fmaf((qq).w, (py), P1); P2 = fmaf((qq).w, (pz), P2); } while (0)

#define CCHUNK(C_) do { \
    CRES((C_).q0, (C_).p0.x, (C_).p0.y, (C_).p0.z); \
    CRES((C_).q1, (C_).p0.w, (C_).p1.x, (C_).p1.y); \
    CRES((C_).q2, (C_).p1.z, (C_).p1.w, (C_).p2.x); \
    CRES((C_).q3, (C_).p2.y, (C_).p2.z, (C_).p2.w); } while (0)

#define TRES(qq, px, py, pz) do { \
    float dx = fmaf(Rv[0], (px), fmaf(Rv[1], (py), fmaf(Rv[2], (pz), -Rv[9])))  - (qq).x; \
    float dy = fmaf(Rv[3], (px), fmaf(Rv[4], (py), fmaf(Rv[5], (pz), -Rv[10]))) - (qq).y; \
    float dz = fmaf(Rv[6], (px), fmaf(Rv[7], (py), fmaf(Rv[8], (pz), -Rv[11]))) - (qq).z; \
    float dsq = fmaf(dx, dx, fmaf(dy, dy, dz * dz)); \
    acc += (qq).w * rcp_fast(fmaf(dsq, invd0, 1.0f)); } while (0)

#define TCHUNK(C_) do { \
    TRES((C_).q0, (C_).p0.x, (C_).p0.y, (C_).p0.z); \
    TRES((C_).q1, (C_).p0.w, (C_).p1.x, (C_).p1.y); \
    TRES((C_).q2, (C_).p1.z, (C_).p1.w, (C_).p2.x); \
    TRES((C_).q3, (C_).p2.y, (C_).p2.z, (C_).p2.w); } while (0)

__global__ void __launch_bounds__(TPB, 2) k_main(const float* __restrict__ pred,
                                                 float* __restrict__ out) {
    int tid = threadIdx.x;
    int lane = tid & 31;
    const float4* __restrict__ p4 = reinterpret_cast<const float4*>(pred);
    float invLt = g_stats[4];
    float invd0 = g_stats[5];

    // ============ phase 1: covariance (warp-autonomous, work-stealing) ==========
    for (;;) {
        unsigned idx;
        if (lane == 0) idx = atomicAdd(&g_ctrA, 1u);
        idx = __shfl_sync(0xffffffffu, idx, 0);
        if (idx >= NITEMS) break;
        int s = idx >> 2, q = idx & 3;
        const float4* pp = p4 + (size_t)s * 3072 + q * 768;
        int rb = q * 1024;

        float S00 = 0, S01 = 0, S02 = 0, S10 = 0, S11 = 0, S12 = 0,
              S20 = 0, S21 = 0, S22 = 0, P0 = 0, P1 = 0, P2 = 0;
        Ck A, B;
        LOADC(A, pp, rb, 0);
        LOADC(B, pp, rb, 1);
        CCHUNK(A); LOADC(A, pp, rb, 2);
        CCHUNK(B); LOADC(B, pp, rb, 3);
        CCHUNK(A); LOADC(A, pp, rb, 4);
        CCHUNK(B); LOADC(B, pp, rb, 5);
        CCHUNK(A); LOADC(A, pp, rb, 6);
        CCHUNK(B); LOADC(B, pp, rb, 7);
        CCHUNK(A);
        CCHUNK(B);

        float vals[12] = {S00, S01, S02, S10, S11, S12, S20, S21, S22, P0, P1, P2};
        float outv[12];
#pragma unroll
        for (int k = 0; k < 12; k++) outv[k] = warpsum(vals[k]);
        if (lane == 0) {
#pragma unroll
            for (int k = 0; k < 12; k++) g_Spart[idx * 12 + k] = outv[k];
        }
    }
    grid_barrier();

    // ============ phase 2: rotations (4 samples per block, threads 0..3) ========
    if (tid < 4) {
        int s = blockIdx.x * 4 + tid;
        if (s < NS) {
            float Sf[12];
#pragma unroll
            for (int i = 0; i < 12; i++) {
                float v = 0.f;
#pragma unroll
                for (int j = 0; j < 4; j++) v += __ldcg(&g_Spart[(s * 4 + j) * 12 + i]);
                Sf[i] = v;
            }
            float Sxx = Sf[0], Sxy = Sf[1], Sxz = Sf[2];
            float Syx = Sf[3], Syy = Sf[4], Syz = Sf[5];
            float Szx = Sf[6], Szy = Sf[7], Szz = Sf[8];

            float A[4][4];
            A[0][0] = Sxx + Syy + Szz; A[0][1] = Syz - Szy;          A[0][2] = Szx - Sxz;          A[0][3] = Sxy - Syx;
            A[1][1] = Sxx - Syy - Szz; A[1][2] = Sxy + Syx;          A[1][3] = Szx + Sxz;
            A[2][2] = -Sxx + Syy - Szz; A[2][3] = Syz + Szy;
            A[3][3] = -Sxx - Syy + Szz;
            A[1][0] = A[0][1]; A[2][0] = A[0][2]; A[3][0] = A[0][3];
            A[2][1] = A[1][2]; A[3][1] = A[1][3]; A[3][2] = A[2][3];
            float V[4][4] = {{1,0,0,0},{0,1,0,0},{0,0,1,0},{0,0,0,1}};

            for (int sweep = 0; sweep < 4; sweep++) {
#pragma unroll
                for (int p = 0; p < 3; p++) {
#pragma unroll
                    for (int qq = p + 1; qq < 4; qq++) {
                        float apq = A[p][qq];
                        float scale = fabsf(A[p][p]) + fabsf(A[qq][qq]);
                        if (fabsf(apq) > 1e-12f * scale + 1e-30f) {
                            float theta = (A[qq][qq] - A[p][p]) / (2.0f * apq);
                            float t = 1.0f / (fabsf(theta) + sqrtf(theta * theta + 1.0f));
                            if (theta < 0.0f) t = -t;
                            float cth = 1.0f / sqrtf(t * t + 1.0f);
                            float sth = t * cth;
#pragma unroll
                            for (int r = 0; r < 4; r++) {
                                float arp = A[r][p], arq = A[r][qq];
                                A[r][p] = arp * cth - arq * sth;
                                A[r][qq] = arp * sth + arq * cth;
                            }
#pragma unroll
                            for (int r = 0; r < 4; r++) {
                                float apr = A[p][r], aqr = A[qq][r];
                                A[p][r] = apr * cth - aqr * sth;
                                A[qq][r] = apr * sth + aqr * cth;
                            }
#pragma unroll
                            for (int r = 0; r < 4; r++) {
                                float vrp = V[r][p], vrq = V[r][qq];
                                V[r][p] = vrp * cth - vrq * sth;
                                V[r][qq] = vrp * sth + vrq * cth;
                            }
                        }
                    }
                }
            }

            int kk = 0;
            float best = A[0][0];
#pragma unroll
            for (int i = 1; i < 4; i++) if (A[i][i] > best) { best = A[i][i]; kk = i; }
            float q0 = V[0][kk], qx = V[1][kk], qy = V[2][kk], qz = V[3][kk];

            float R[3][3];
            R[0][0] = q0*q0 + qx*qx - qy*qy - qz*qz;
            R[0][1] = 2.0f * (qx*qy - q0*qz);
            R[0][2] = 2.0f * (qx*qz + q0*qy);
            R[1][0] = 2.0f * (qy*qx + q0*qz);
            R[1][1] = q0*q0 - qx*qx + qy*qy - qz*qz;
            R[1][2] = 2.0f * (qy*qz - q0*qx);
            R[2][0] = 2.0f * (qz*qx - q0*qy);
            R[2][1] = 2.0f * (qz*qy + q0*qx);
            R[2][2] = q0*q0 - qx*qx - qy*qy + qz*qz;

            float Sm[3][3] = {{Sxx,Sxy,Sxz},{Syx,Syy,Syz},{Szx,Szy,Szz}};
            float obj = 0.f, objT = 0.f;
#pragma unroll
            for (int i = 0; i < 3; i++)
#pragma unroll
                for (int j = 0; j < 3; j++) {
                    obj  += R[i][j] * Sm[j][i];
                    objT += R[j][i] * Sm[j][i];
                }
            if (objT > obj) {
#pragma unroll
                for (int i = 0; i < 3; i++)
#pragma unroll
                    for (int j = i + 1; j < 3; j++) {
                        float tmp = R[i][j]; R[i][j] = R[j][i]; R[j][i] = tmp;
                    }
            }

            float pm0 = Sf[9] * invLt, pm1 = Sf[10] * invLt, pm2 = Sf[11] * invLt;
            int base = s * 12;
            g_RT[base + 0] = R[0][0]; g_RT[base + 1] = R[0][1]; g_RT[base + 2] = R[0][2];
            g_RT[base + 3] = R[1][0]; g_RT[base + 4] = R[1][1]; g_RT[base + 5] = R[1][2];
            g_RT[base + 6] = R[2][0]; g_RT[base + 7] = R[2][1]; g_RT[base + 8] = R[2][2];
            g_RT[base + 9]  = R[0][0]*pm0 + R[0][1]*pm1 + R[0][2]*pm2;
            g_RT[base + 10] = R[1][0]*pm0 + R[1][1]*pm1 + R[1][2]*pm2;
            g_RT[base + 11] = R[2][0]*pm0 + R[2][1]*pm1 + R[2][2]*pm2;
        }
    }
    grid_barrier();

    // ============ phase 3: TM score (warp-autonomous, work-stealing) ============
    for (;;) {
        unsigned idx;
        if (lane == 0) idx = atomicAdd(&g_ctrB, 1u);
        idx = __shfl_sync(0xffffffffu, idx, 0);
        if (idx >= NITEMS) break;
        int s = idx >> 2, q = idx & 3;
        const float4* pp = p4 + (size_t)s * 3072 + q * 768;
        int rb = q * 1024;

        float Rv[12];
#pragma unroll
        for (int i = 0; i < 12; i++) Rv[i] = __ldcg(&g_RT[s * 12 + i]);

        float acc = 0.f;
        Ck A, B;
        LOADC(A, pp, rb, 0);
        LOADC(B, pp, rb, 1);
        TCHUNK(A); LOADC(A, pp, rb, 2);
        TCHUNK(B); LOADC(B, pp, rb, 3);
        TCHUNK(A); LOADC(A, pp, rb, 4);
        TCHUNK(B); LOADC(B, pp, rb, 5);
        TCHUNK(A); LOADC(A, pp, rb, 6);
        TCHUNK(B); LOADC(B, pp, rb, 7);
        TCHUNK(A);
        TCHUNK(B);

        acc = warpsum(acc);
        if (lane == 0) g_tmpart[idx] = acc;
    }
    grid_barrier();

    // ============ phase 4: output ===============================================
    if (tid < 4) {
        int s = blockIdx.x * 4 + tid;
        if (s < NS) {
            float v = __ldcg(&g_tmpart[4 * s + 0]) + __ldcg(&g_tmpart[4 * s + 1])
                    + __ldcg(&g_tmpart[4 * s + 2]) + __ldcg(&g_tmpart[4 * s + 3]);
            out[s] = v * invLt;
        }
    }
}

// ---------------- launch ----------------
extern "C" void kernel_launch(void* const* d_in, const int* in_sizes, int n_in,
                              void* d_out, int out_size) {
    const float* pred = (const float*)d_in[0];
    const float* truec = (const float*)d_in[1];
    const int* mask = (const int*)d_in[2];
    float* out = (float*)d_out;

    k_pre<<<1, PRE_T>>>(truec, mask);
    k_main<<<GRIDP, TPB>>>(pred, out);
}

// round 15
// speedup vs baseline: 1.0787x; 1.0787x over previous
#include <cuda_runtime.h>
#include <math.h>
#include <stdint.h>

#define NS 1024
#define NR 4096
#define NSM 148
#define GRIDP (2 * NSM)        // 296 blocks, exactly 2 per SM (96KB smem forces it)
#define TPB 256
#define STAGE_F4 1536          // half-sample tile: 2048 residues = 1536 float4 = 24KB
#define STAGE_BYTES (STAGE_F4 * 16)
#define NSTAGE 4
#define DYN_SMEM (NSTAGE * STAGE_BYTES)   // 96KB

// ---------------- scratch ----------------
__device__ __align__(16) float4 g_wt4[NR];  // (w*t_c0, w*t_c1, w*t_c2, w)
__device__ float g_stats[8];                // [4]=1/Lt, [5]=1/d0^2
__device__ float g_Spart[NS * 2 * 12];      // per (sample, half): S(9), P(3)
__device__ float g_RT[NS * 12];             // per sample: R(9), c(3)
__device__ float g_tmpart[NS * 2];
__device__ unsigned g_barA = 0, g_barG = 0;

__device__ __forceinline__ float warpsum(float v) {
#pragma unroll
    for (int o = 16; o; o >>= 1) v += __shfl_down_sync(0xffffffffu, v, o);
    return v;
}

__device__ __forceinline__ float rcp_fast(float x) {
    float r;
    asm("rcp.approx.f32 %0, %1;" : "=f"(r) : "f"(x));
    return r;
}

__device__ __forceinline__ void cpa16(uint32_t d, const void* s) {
    asm volatile("cp.async.cg.shared.global [%0], [%1], 16;" :: "r"(d), "l"(s));
}
__device__ __forceinline__ void cpcommit() { asm volatile("cp.async.commit_group;"); }
template <int N> __device__ __forceinline__ void cpwait() {
    asm volatile("cp.async.wait_group %0;" :: "n"(N));
}

// sense-reversing grid barrier; all GRIDP blocks co-resident (2/SM via smem)
__device__ __forceinline__ void grid_barrier() {
    __threadfence();
    __syncthreads();
    if (threadIdx.x == 0) {
        unsigned gen = atomicAdd(&g_barG, 0u);
        unsigned t = atomicAdd(&g_barA, 1u);
        if (t == GRIDP - 1) {
            atomicExch(&g_barA, 0u);
            __threadfence();
            atomicAdd(&g_barG, 1u);
        } else {
            while (atomicAdd(&g_barG, 0u) == gen) __nanosleep(64);
        }
    }
    __syncthreads();
}

// ---------------- kernel A: true stats + wt4 companion ----------------
#define PRE_T 1024
__global__ void k_pre(const float* __restrict__ truec, const int* __restrict__ mask) {
    int tid = threadIdx.x;
    float ws = 0.f, wt0 = 0.f, wt1 = 0.f, wt2 = 0.f;
    for (int l = tid; l < NR; l += PRE_T) {
        float w = (mask[l] != 0) ? 1.0f : 0.0f;
        ws += w;
        wt0 += w * truec[l * 3 + 0];
        wt1 += w * truec[l * 3 + 1];
        wt2 += w * truec[l * 3 + 2];
    }
    __shared__ float sm[4][32];
    __shared__ float s_tm[3];
    int lane = tid & 31, wid = tid >> 5;
    ws = warpsum(ws); wt0 = warpsum(wt0); wt1 = warpsum(wt1); wt2 = warpsum(wt2);
    if (lane == 0) { sm[0][wid] = ws; sm[1][wid] = wt0; sm[2][wid] = wt1; sm[3][wid] = wt2; }
    __syncthreads();
    if (tid == 0) {
        float Lt = 0.f, a = 0.f, b = 0.f, c = 0.f;
        for (int i = 0; i < 32; i++) { Lt += sm[0][i]; a += sm[1][i]; b += sm[2][i]; c += sm[3][i]; }
        float inv = 1.0f / Lt;
        float d0 = (Lt <= 15.0f) ? 0.5f : (1.24f * cbrtf(Lt - 15.0f) - 1.8f);
        d0 = fmaxf(d0, 0.5f);
        g_stats[0] = a * inv; g_stats[1] = b * inv; g_stats[2] = c * inv;
        g_stats[3] = Lt; g_stats[4] = inv; g_stats[5] = 1.0f / (d0 * d0);
        s_tm[0] = a * inv; s_tm[1] = b * inv; s_tm[2] = c * inv;
    }
    __syncthreads();
    float m0 = s_tm[0], m1 = s_tm[1], m2 = s_tm[2];
    for (int l = tid; l < NR; l += PRE_T) {
        float w = (mask[l] != 0) ? 1.0f : 0.0f;
        float4 v;
        v.x = w * (truec[l * 3 + 0] - m0);
        v.y = w * (truec[l * 3 + 1] - m1);
        v.z = w * (truec[l * 3 + 2] - m2);
        v.w = w;
        g_wt4[l] = v;
    }
}

// ---------------- main persistent kernel -----------------------------------
// block = (col, h): samples col, col+148, ...; half h = residues [h*2048, h*2048+2048)
// thread t owns groups g0 = t, g1 = t + 256 (4 residues each) of the tile.

__global__ void __launch_bounds__(TPB, 2) k_main(const float* __restrict__ pred,
                                                 float* __restrict__ out) {
    extern __shared__ float s_ring[];   // NSTAGE * 1536 float4
    __shared__ float red[12][8];
    __shared__ float Psh[12];

    int b = blockIdx.x;
    int col = b >> 1, h = b & 1;
    int tid = threadIdx.x;
    int lane = tid & 31, wid = tid >> 5;
    int ns = 6 + (col < 136 ? 1 : 0);   // samples this col handles

    float invLt = g_stats[4];
    float invd0 = g_stats[5];

    uint32_t smem_base;
    {
        void* p = s_ring;
        asm("{ .reg .u64 t; cvta.to.shared.u64 t, %1; cvt.u32.u64 %0, t; }"
            : "=r"(smem_base) : "l"(p));
    }

    // companions: 8 residues per thread, loaded once per block lifetime
    float4 q[8];
    {
        const float4* wp = g_wt4 + h * 2048;
#pragma unroll
        for (int i = 0; i < 4; i++) q[i] = wp[4 * tid + i];
#pragma unroll
        for (int i = 0; i < 4; i++) q[4 + i] = wp[4 * (tid + 256) + i];
    }

    const float4* __restrict__ p4 = reinterpret_cast<const float4*>(pred);

#define ISSUE(j_) do { \
    int ss_ = col + (j_) * NSM; \
    if (ss_ < NS) { \
        const float4* gp_ = p4 + (size_t)ss_ * 3072 + h * STAGE_F4; \
        uint32_t sb_ = smem_base + ((j_) & 3) * STAGE_BYTES; \
        cpa16(sb_ + (tid)           * 16, gp_ + tid); \
        cpa16(sb_ + (tid + 256)     * 16, gp_ + tid + 256); \
        cpa16(sb_ + (tid + 512)     * 16, gp_ + tid + 512); \
        cpa16(sb_ + (tid + 768)     * 16, gp_ + tid + 768); \
        cpa16(sb_ + (tid + 1024)    * 16, gp_ + tid + 1024); \
        cpa16(sb_ + (tid + 1280)    * 16, gp_ + tid + 1280); \
    } \
    cpcommit(); } while (0)

    // ============ phase 1: covariance ==========================================
    ISSUE(0); ISSUE(1); ISSUE(2);
    for (int i = 0; i < ns; i++) {
        ISSUE(i + 3);
        cpwait<3>();
        __syncthreads();

        const float4* st = reinterpret_cast<const float4*>(s_ring) + (i & 3) * STAGE_F4;
        float S00 = 0, S01 = 0, S02 = 0, S10 = 0, S11 = 0, S12 = 0,
              S20 = 0, S21 = 0, S22 = 0, P0 = 0, P1 = 0, P2 = 0;
#define CRES(qq, px, py, pz) do { \
    S00 = fmaf((px), (qq).x, S00); S01 = fmaf((px), (qq).y, S01); S02 = fmaf((px), (qq).z, S02); \
    S10 = fmaf((py), (qq).x, S10); S11 = fmaf((py), (qq).y, S11); S12 = fmaf((py), (qq).z, S12); \
    S20 = fmaf((pz), (qq).x, S20); S21 = fmaf((pz), (qq).y, S21); S22 = fmaf((pz), (qq).z, S22); \
    P0 = fmaf((qq).w, (px), P0); P1 = fmaf((qq).w, (py), P1); P2 = fmaf((qq).w, (pz), P2); } while (0)
#pragma unroll
        for (int k = 0; k < 2; k++) {
            int g = tid + k * 256;
            float4 A = st[3 * g], B = st[3 * g + 1], C = st[3 * g + 2];
            CRES(q[4 * k + 0], A.x, A.y, A.z);
            CRES(q[4 * k + 1], A.w, B.x, B.y);
            CRES(q[4 * k + 2], B.z, B.w, C.x);
            CRES(q[4 * k + 3], C.y, C.z, C.w);
        }

        float vals[12] = {S00, S01, S02, S10, S11, S12, S20, S21, S22, P0, P1, P2};
#pragma unroll
        for (int k = 0; k < 12; k++) {
            float v = warpsum(vals[k]);
            if (lane == 0) red[k][wid] = v;
        }
        __syncthreads();
        int s = col + i * NSM;
        if (tid < 12) {
            float v = 0.f;
#pragma unroll
            for (int j = 0; j < 8; j++) v += red[tid][j];
            g_Spart[(s * 2 + h) * 12 + tid] = v;
        }
        __syncthreads();
    }
    cpwait<0>();
    grid_barrier();

    // ============ phase 2: rotations (threads 0..3, 4 samples per block) =======
    if (tid < 4) {
        int s = blockIdx.x * 4 + tid;
        if (s < NS) {
            float Sf[12];
#pragma unroll
            for (int i = 0; i < 12; i++)
                Sf[i] = __ldcg(&g_Spart[(s * 2) * 12 + i]) + __ldcg(&g_Spart[(s * 2 + 1) * 12 + i]);
            float Sxx = Sf[0], Sxy = Sf[1], Sxz = Sf[2];
            float Syx = Sf[3], Syy = Sf[4], Syz = Sf[5];
            float Szx = Sf[6], Szy = Sf[7], Szz = Sf[8];

            float A[4][4];
            A[0][0] = Sxx + Syy + Szz; A[0][1] = Syz - Szy;          A[0][2] = Szx - Sxz;          A[0][3] = Sxy - Syx;
            A[1][1] = Sxx - Syy - Szz; A[1][2] = Sxy + Syx;          A[1][3] = Szx + Sxz;
            A[2][2] = -Sxx + Syy - Szz; A[2][3] = Syz + Szy;
            A[3][3] = -Sxx - Syy + Szz;
            A[1][0] = A[0][1]; A[2][0] = A[0][2]; A[3][0] = A[0][3];
            A[2][1] = A[1][2]; A[3][1] = A[1][3]; A[3][2] = A[2][3];
            float V[4][4] = {{1,0,0,0},{0,1,0,0},{0,0,1,0},{0,0,0,1}};

            for (int sweep = 0; sweep < 4; sweep++) {
#pragma unroll
                for (int p = 0; p < 3; p++) {
#pragma unroll
                    for (int qq = p + 1; qq < 4; qq++) {
                        float apq = A[p][qq];
                        float scale = fabsf(A[p][p]) + fabsf(A[qq][qq]);
                        if (fabsf(apq) > 1e-12f * scale + 1e-30f) {
                            float theta = (A[qq][qq] - A[p][p]) / (2.0f * apq);
                            float t = 1.0f / (fabsf(theta) + sqrtf(theta * theta + 1.0f));
                            if (theta < 0.0f) t = -t;
                            float cth = 1.0f / sqrtf(t * t + 1.0f);
                            float sth = t * cth;
#pragma unroll
                            for (int r = 0; r < 4; r++) {
                                float arp = A[r][p], arq = A[r][qq];
                                A[r][p] = arp * cth - arq * sth;
                                A[r][qq] = arp * sth + arq * cth;
                            }
#pragma unroll
                            for (int r = 0; r < 4; r++) {
                                float apr = A[p][r], aqr = A[qq][r];
                                A[p][r] = apr * cth - aqr * sth;
                                A[qq][r] = apr * sth + aqr * cth;
                            }
#pragma unroll
                            for (int r = 0; r < 4; r++) {
                                float vrp = V[r][p], vrq = V[r][qq];
                                V[r][p] = vrp * cth - vrq * sth;
                                V[r][qq] = vrp * sth + vrq * cth;
                            }
                        }
                    }
                }
            }

            int kk = 0;
            float best = A[0][0];
#pragma unroll
            for (int i = 1; i < 4; i++) if (A[i][i] > best) { best = A[i][i]; kk = i; }
            float q0 = V[0][kk], qx = V[1][kk], qy = V[2][kk], qz = V[3][kk];

            float R[3][3];
            R[0][0] = q0*q0 + qx*qx - qy*qy - qz*qz;
            R[0][1] = 2.0f * (qx*qy - q0*qz);
            R[0][2] = 2.0f * (qx*qz + q0*qy);
            R[1][0] = 2.0f * (qy*qx + q0*qz);
            R[1][1] = q0*q0 - qx*qx + qy*qy - qz*qz;
            R[1][2] = 2.0f * (qy*qz - q0*qx);
            R[2][0] = 2.0f * (qz*qx - q0*qy);
            R[2][1] = 2.0f * (qz*qy + q0*qx);
            R[2][2] = q0*q0 - qx*qx - qy*qy + qz*qz;

            float Sm[3][3] = {{Sxx,Sxy,Sxz},{Syx,Syy,Syz},{Szx,Szy,Szz}};
            float obj = 0.f, objT = 0.f;
#pragma unroll
            for (int i = 0; i < 3; i++)
#pragma unroll
                for (int j = 0; j < 3; j++) {
                    obj  += R[i][j] * Sm[j][i];
                    objT += R[j][i] * Sm[j][i];
                }
            if (objT > obj) {
#pragma unroll
                for (int i = 0; i < 3; i++)
#pragma unroll
                    for (int j = i + 1; j < 3; j++) {
                        float tmp = R[i][j]; R[i][j] = R[j][i]; R[j][i] = tmp;
                    }
            }

            float pm0 = Sf[9] * invLt, pm1 = Sf[10] * invLt, pm2 = Sf[11] * invLt;
            int base = s * 12;
            g_RT[base + 0] = R[0][0]; g_RT[base + 1] = R[0][1]; g_RT[base + 2] = R[0][2];
            g_RT[base + 3] = R[1][0]; g_RT[base + 4] = R[1][1]; g_RT[base + 5] = R[1][2];
            g_RT[base + 6] = R[2][0]; g_RT[base + 7] = R[2][1]; g_RT[base + 8] = R[2][2];
            g_RT[base + 9]  = R[0][0]*pm0 + R[0][1]*pm1 + R[0][2]*pm2;
            g_RT[base + 10] = R[1][0]*pm0 + R[1][1]*pm1 + R[1][2]*pm2;
            g_RT[base + 11] = R[2][0]*pm0 + R[2][1]*pm1 + R[2][2]*pm2;
        }
    }
    grid_barrier();

    // ============ phase 3: TM score ============================================
    ISSUE(0); ISSUE(1); ISSUE(2);
    for (int i = 0; i < ns; i++) {
        int s = col + i * NSM;
        ISSUE(i + 3);
        if (tid < 12) Psh[tid] = __ldcg(&g_RT[s * 12 + tid]);
        cpwait<3>();
        __syncthreads();

        float R00 = Psh[0], R01 = Psh[1], R02 = Psh[2];
        float R10 = Psh[3], R11 = Psh[4], R12 = Psh[5];
        float R20 = Psh[6], R21 = Psh[7], R22 = Psh[8];
        float cc0 = Psh[9], cc1 = Psh[10], cc2 = Psh[11];

        const float4* st = reinterpret_cast<const float4*>(s_ring) + (i & 3) * STAGE_F4;
        float acc = 0.f;
#define TRES(qq, px, py, pz) do { \
    float dx = fmaf(R00, (px), fmaf(R01, (py), fmaf(R02, (pz), -cc0))) - (qq).x; \
    float dy = fmaf(R10, (px), fmaf(R11, (py), fmaf(R12, (pz), -cc1))) - (qq).y; \
    float dz = fmaf(R20, (px), fmaf(R21, (py), fmaf(R22, (pz), -cc2))) - (qq).z; \
    float dsq = fmaf(dx, dx, fmaf(dy, dy, dz * dz)); \
    acc += (qq).w * rcp_fast(fmaf(dsq, invd0, 1.0f)); } while (0)
#pragma unroll
        for (int k = 0; k < 2; k++) {
            int g = tid + k * 256;
            float4 A = st[3 * g], B = st[3 * g + 1], C = st[3 * g + 2];
            TRES(q[4 * k + 0], A.x, A.y, A.z);
            TRES(q[4 * k + 1], A.w, B.x, B.y);
            TRES(q[4 * k + 2], B.z, B.w, C.x);
            TRES(q[4 * k + 3], C.y, C.z, C.w);
        }

        acc = warpsum(acc);
        if (lane == 0) red[0][wid] = acc;
        __syncthreads();
        if (tid == 0) {
            float v = 0.f;
#pragma unroll
            for (int j = 0; j < 8; j++) v += red[0][j];
            g_tmpart[s * 2 + h] = v;
        }
        __syncthreads();
    }
    cpwait<0>();
    grid_barrier();

    // ============ phase 4: output ==============================================
    if (tid < 4) {
        int s = blockIdx.x * 4 + tid;
        if (s < NS) {
            float v = __ldcg(&g_tmpart[2 * s]) + __ldcg(&g_tmpart[2 * s + 1]);
            out[s] = v * invLt;
        }
    }
}

// ---------------- launch ----------------
extern "C" void kernel_launch(void* const* d_in, const int* in_sizes, int n_in,
                              void* d_out, int out_size) {
    const float* pred = (const float*)d_in[0];
    const float* truec = (const float*)d_in[1];
    const int* mask = (const int*)d_in[2];
    float* out = (float*)d_out;

    cudaFuncSetAttribute(k_main, cudaFuncAttributeMaxDynamicSharedMemorySize, DYN_SMEM);

    k_pre<<<1, PRE_T>>>(truec, mask);
    k_main<<<GRIDP, TPB, DYN_SMEM>>>(pred, out);
}

// round 17
// speedup vs baseline: 1.2902x; 1.1961x over previous
#include <cuda_runtime.h>
#include <math.h>
#include <stdint.h>

#define NS 1024
#define NR 4096
#define GRID 296            // 2 blocks per SM, forced by 96KB dynamic smem
#define TPB 256
#define RPT 16              // residues per thread
#define TILE_F 12288        // floats per sample (4096*3)
#define TILE_BYTES 49152
#define DYN_SMEM (2 * TILE_BYTES)

__device__ __forceinline__ float warpsum(float v) {
#pragma unroll
    for (int o = 16; o; o >>= 1) v += __shfl_down_sync(0xffffffffu, v, o);
    return v;
}

__device__ __forceinline__ float rcp_fast(float x) {
    float r;
    asm("rcp.approx.f32 %0, %1;" : "=f"(r) : "f"(x));
    return r;
}

__device__ __forceinline__ uint32_t smem_u32(const void* p) {
    uint32_t a;
    asm("{ .reg .u64 t; cvta.to.shared.u64 t, %1; cvt.u32.u64 %0, t; }" : "=r"(a) : "l"(p));
    return a;
}

__device__ __forceinline__ void mbar_init(uint32_t mb, unsigned cnt) {
    asm volatile("mbarrier.init.shared.b64 [%0], %1;" :: "r"(mb), "r"(cnt) : "memory");
}
__device__ __forceinline__ void mbar_expect_tx(uint32_t mb, unsigned bytes) {
    asm volatile("mbarrier.arrive.expect_tx.shared.b64 _, [%0], %1;" :: "r"(mb), "r"(bytes) : "memory");
}
__device__ __forceinline__ void tma_bulk_1d(uint32_t dst, const void* src, unsigned bytes, uint32_t mb) {
    asm volatile(
        "cp.async.bulk.shared::cluster.global.mbarrier::complete_tx::bytes [%0], [%1], %2, [%3];"
        :: "r"(dst), "l"(src), "r"(bytes), "r"(mb) : "memory");
}
__device__ __forceinline__ void mbar_wait(uint32_t mb, int phase) {
    asm volatile(
        "{\n\t"
        ".reg .pred P;\n\t"
        "W_%=:\n\t"
        "mbarrier.try_wait.parity.acquire.cta.shared::cta.b64 P, [%0], %1, 0x989680;\n\t"
        "@P bra.uni D_%=;\n\t"
        "bra.uni W_%=;\n\t"
        "D_%=:\n\t"
        "}"
        :: "r"(mb), "r"(phase) : "memory");
}

__global__ void __launch_bounds__(TPB, 2) k_fused(const float* __restrict__ pred,
                                                  const float* __restrict__ truec,
                                                  const int* __restrict__ mask,
                                                  float* __restrict__ out) {
    extern __shared__ float ring[];       // 2 x TILE_F floats
    __shared__ float red[12][8];
    __shared__ float bc[6];               // m0 m1 m2 invLt invd0
    __shared__ float Ssh[12];
    __shared__ float Psh[12];
    __shared__ __align__(8) unsigned long long mbar_store[2];

    int b = blockIdx.x;
    int tid = threadIdx.x;
    int lane = tid & 31, wid = tid >> 5;
    int ns = (b < 136) ? 4 : 3;           // 136*4 + 160*3 = 1024

    uint32_t sb = smem_u32(ring);
    uint32_t mb0 = smem_u32(&mbar_store[0]);
    uint32_t mb1 = smem_u32(&mbar_store[1]);

    // -------- init barriers + launch first two TMA loads (overlap stats) -----
    if (tid == 0) {
        mbar_init(mb0, 1);
        mbar_init(mb1, 1);
        asm volatile("fence.proxy.async.shared::cta;" ::: "memory");
        mbar_expect_tx(mb0, TILE_BYTES);
        tma_bulk_1d(sb, pred + (size_t)b * TILE_F, TILE_BYTES, mb0);
        if (ns >= 2) {
            mbar_expect_tx(mb1, TILE_BYTES);
            tma_bulk_1d(sb + TILE_BYTES, pred + (size_t)(b + GRID) * TILE_F, TILE_BYTES, mb1);
        }
    }

    // -------- stats (redundant per block) + companions in registers ----------
    float W[RPT], TX[RPT], TY[RPT], TZ[RPT];
    {
        float ws = 0.f, s0 = 0.f, s1 = 0.f, s2 = 0.f;
#pragma unroll
        for (int k = 0; k < RPT; k++) {
            int l = tid + k * 256;
            float w = (mask[l] != 0) ? 1.0f : 0.0f;
            W[k] = w;
            TX[k] = truec[3 * l + 0];
            TY[k] = truec[3 * l + 1];
            TZ[k] = truec[3 * l + 2];
            ws += w; s0 += w * TX[k]; s1 += w * TY[k]; s2 += w * TZ[k];
        }
        float vals[4] = {ws, s0, s1, s2};
#pragma unroll
        for (int k = 0; k < 4; k++) {
            float v = warpsum(vals[k]);
            if (lane == 0) red[k][wid] = v;
        }
        __syncthreads();
        if (tid == 0) {
            float Lt = 0.f, a = 0.f, bb = 0.f, c = 0.f;
#pragma unroll
            for (int i = 0; i < 8; i++) { Lt += red[0][i]; a += red[1][i]; bb += red[2][i]; c += red[3][i]; }
            float inv = 1.0f / Lt;
            float d0 = (Lt <= 15.0f) ? 0.5f : (1.24f * cbrtf(Lt - 15.0f) - 1.8f);
            d0 = fmaxf(d0, 0.5f);
            bc[0] = a * inv; bc[1] = bb * inv; bc[2] = c * inv;
            bc[3] = inv; bc[4] = 1.0f / (d0 * d0);
        }
        __syncthreads();
        float m0 = bc[0], m1 = bc[1], m2 = bc[2];
#pragma unroll
        for (int k = 0; k < RPT; k++) {
            TX[k] = W[k] * (TX[k] - m0);
            TY[k] = W[k] * (TY[k] - m1);
            TZ[k] = W[k] * (TZ[k] - m2);
        }
    }
    float invLt = bc[3], invd0 = bc[4];

    // -------- per-sample pipeline -------------------------------------------
    int ph0 = 0, ph1 = 0;
    for (int i = 0; i < ns; i++) {
        int k = i & 1;
        int s = b + i * GRID;
        uint32_t mb = k ? mb1 : mb0;
        int ph = k ? ph1 : ph0;
        mbar_wait(mb, ph);
        if (k) ph1 ^= 1; else ph0 ^= 1;

        const float* st = ring + k * TILE_F;

        // ---- covariance ----
        float S00 = 0, S01 = 0, S02 = 0, S10 = 0, S11 = 0, S12 = 0,
              S20 = 0, S21 = 0, S22 = 0, P0 = 0, P1 = 0, P2 = 0;
#pragma unroll
        for (int kk = 0; kk < RPT; kk++) {
            int o = 3 * tid + kk * 768;
            float px = st[o], py = st[o + 1], pz = st[o + 2];
            S00 = fmaf(px, TX[kk], S00); S01 = fmaf(px, TY[kk], S01); S02 = fmaf(px, TZ[kk], S02);
            S10 = fmaf(py, TX[kk], S10); S11 = fmaf(py, TY[kk], S11); S12 = fmaf(py, TZ[kk], S12);
            S20 = fmaf(pz, TX[kk], S20); S21 = fmaf(pz, TY[kk], S21); S22 = fmaf(pz, TZ[kk], S22);
            P0 = fmaf(W[kk], px, P0); P1 = fmaf(W[kk], py, P1); P2 = fmaf(W[kk], pz, P2);
        }
        {
            float vals[12] = {S00, S01, S02, S10, S11, S12, S20, S21, S22, P0, P1, P2};
#pragma unroll
            for (int j = 0; j < 12; j++) {
                float v = warpsum(vals[j]);
                if (lane == 0) red[j][wid] = v;
            }
        }
        __syncthreads();
        if (tid < 12) {
            float v = 0.f;
#pragma unroll
            for (int j = 0; j < 8; j++) v += red[tid][j];
            Ssh[tid] = v;
        }
        __syncthreads();

        // ---- rotation (thread 0; other block on the SM fills the gap) ----
        if (tid == 0) {
            float Sxx = Ssh[0], Sxy = Ssh[1], Sxz = Ssh[2];
            float Syx = Ssh[3], Syy = Ssh[4], Syz = Ssh[5];
            float Szx = Ssh[6], Szy = Ssh[7], Szz = Ssh[8];

            float A[4][4];
            A[0][0] = Sxx + Syy + Szz; A[0][1] = Syz - Szy;          A[0][2] = Szx - Sxz;          A[0][3] = Sxy - Syx;
            A[1][1] = Sxx - Syy - Szz; A[1][2] = Sxy + Syx;          A[1][3] = Szx + Sxz;
            A[2][2] = -Sxx + Syy - Szz; A[2][3] = Syz + Szy;
            A[3][3] = -Sxx - Syy + Szz;
            A[1][0] = A[0][1]; A[2][0] = A[0][2]; A[3][0] = A[0][3];
            A[2][1] = A[1][2]; A[3][1] = A[1][3]; A[3][2] = A[2][3];
            float V[4][4] = {{1,0,0,0},{0,1,0,0},{0,0,1,0},{0,0,0,1}};

            for (int sweep = 0; sweep < 4; sweep++) {
#pragma unroll
                for (int p = 0; p < 3; p++) {
#pragma unroll
                    for (int q = p + 1; q < 4; q++) {
                        float apq = A[p][q];
                        float scale = fabsf(A[p][p]) + fabsf(A[q][q]);
                        if (fabsf(apq) > 1e-12f * scale + 1e-30f) {
                            float theta = (A[q][q] - A[p][p]) / (2.0f * apq);
                            float t = 1.0f / (fabsf(theta) + sqrtf(theta * theta + 1.0f));
                            if (theta < 0.0f) t = -t;
                            float cth = 1.0f / sqrtf(t * t + 1.0f);
                            float sth = t * cth;
#pragma unroll
                            for (int r = 0; r < 4; r++) {
                                float arp = A[r][p], arq = A[r][q];
                                A[r][p] = arp * cth - arq * sth;
                                A[r][q] = arp * sth + arq * cth;
                            }
#pragma unroll
                            for (int r = 0; r < 4; r++) {
                                float apr = A[p][r], aqr = A[q][r];
                                A[p][r] = apr * cth - aqr * sth;
                                A[q][r] = apr * sth + aqr * cth;
                            }
#pragma unroll
                            for (int r = 0; r < 4; r++) {
                                float vrp = V[r][p], vrq = V[r][q];
                                V[r][p] = vrp * cth - vrq * sth;
                                V[r][q] = vrp * sth + vrq * cth;
                            }
                        }
                    }
                }
            }

            int km = 0;
            float best = A[0][0];
#pragma unroll
            for (int i2 = 1; i2 < 4; i2++) if (A[i2][i2] > best) { best = A[i2][i2]; km = i2; }
            float q0 = V[0][km], qx = V[1][km], qy = V[2][km], qz = V[3][km];

            float R[3][3];
            R[0][0] = q0*q0 + qx*qx - qy*qy - qz*qz;
            R[0][1] = 2.0f * (qx*qy - q0*qz);
            R[0][2] = 2.0f * (qx*qz + q0*qy);
            R[1][0] = 2.0f * (qy*qx + q0*qz);
            R[1][1] = q0*q0 - qx*qx + qy*qy - qz*qz;
            R[1][2] = 2.0f * (qy*qz - q0*qx);
            R[2][0] = 2.0f * (qz*qx - q0*qy);
            R[2][1] = 2.0f * (qz*qy + q0*qx);
            R[2][2] = q0*q0 - qx*qx - qy*qy + qz*qz;

            float Sm[3][3] = {{Sxx,Sxy,Sxz},{Syx,Syy,Syz},{Szx,Szy,Szz}};
            float obj = 0.f, objT = 0.f;
#pragma unroll
            for (int i2 = 0; i2 < 3; i2++)
#pragma unroll
                for (int j = 0; j < 3; j++) {
                    obj  += R[i2][j] * Sm[j][i2];
                    objT += R[j][i2] * Sm[j][i2];
                }
            if (objT > obj) {
#pragma unroll
                for (int i2 = 0; i2 < 3; i2++)
#pragma unroll
                    for (int j = i2 + 1; j < 3; j++) {
                        float tmp = R[i2][j]; R[i2][j] = R[j][i2]; R[j][i2] = tmp;
                    }
            }

            float pm0 = Ssh[9] * invLt, pm1 = Ssh[10] * invLt, pm2 = Ssh[11] * invLt;
            Psh[0] = R[0][0]; Psh[1] = R[0][1]; Psh[2] = R[0][2];
            Psh[3] = R[1][0]; Psh[4] = R[1][1]; Psh[5] = R[1][2];
            Psh[6] = R[2][0]; Psh[7] = R[2][1]; Psh[8] = R[2][2];
            Psh[9]  = R[0][0]*pm0 + R[0][1]*pm1 + R[0][2]*pm2;
            Psh[10] = R[1][0]*pm0 + R[1][1]*pm1 + R[1][2]*pm2;
            Psh[11] = R[2][0]*pm0 + R[2][1]*pm1 + R[2][2]*pm2;
        }
        __syncthreads();

        // ---- TM pass ----
        float R00 = Psh[0], R01 = Psh[1], R02 = Psh[2];
        float R10 = Psh[3], R11 = Psh[4], R12 = Psh[5];
        float R20 = Psh[6], R21 = Psh[7], R22 = Psh[8];
        float c0 = Psh[9], c1 = Psh[10], c2 = Psh[11];

        float acc = 0.f;
#pragma unroll
        for (int kk = 0; kk < RPT; kk++) {
            int o = 3 * tid + kk * 768;
            float px = st[o], py = st[o + 1], pz = st[o + 2];
            float dx = fmaf(R00, px, fmaf(R01, py, fmaf(R02, pz, -c0))) - TX[kk];
            float dy = fmaf(R10, px, fmaf(R11, py, fmaf(R12, pz, -c1))) - TY[kk];
            float dz = fmaf(R20, px, fmaf(R21, py, fmaf(R22, pz, -c2))) - TZ[kk];
            float dsq = fmaf(dx, dx, fmaf(dy, dy, dz * dz));
            acc += W[kk] * rcp_fast(fmaf(dsq, invd0, 1.0f));
        }
        acc = warpsum(acc);
        if (lane == 0) red[0][wid] = acc;
        __syncthreads();
        if (tid == 0) {
            float v = 0.f;
#pragma unroll
            for (int j = 0; j < 8; j++) v += red[0][j];
            out[s] = v * invLt;
        }
        __syncthreads();   // everyone done reading buffer k before reuse

        // ---- refill this buffer with sample i+2 ----
        if (tid == 0 && i + 2 < ns) {
            mbar_expect_tx(mb, TILE_BYTES);
            tma_bulk_1d(sb + k * TILE_BYTES,
                        pred + (size_t)(b + (i + 2) * GRID) * TILE_F, TILE_BYTES, mb);
        }
    }
}

// ---------------- launch ----------------
extern "C" void kernel_launch(void* const* d_in, const int* in_sizes, int n_in,
                              void* d_out, int out_size) {
    const float* pred = (const float*)d_in[0];
    const float* truec = (const float*)d_in[1];
    const int* mask = (const int*)d_in[2];
    float* out = (float*)d_out;

    cudaFuncSetAttribute(k_fused, cudaFuncAttributeMaxDynamicSharedMemorySize, DYN_SMEM);
    k_fused<<<GRID, TPB, DYN_SMEM>>>(pred, truec, mask, out);
}